// round 10
// baseline (speedup 1.0000x reference)
#include <cuda_runtime.h>
#include <cuda_bf16.h>
#include <cstdint>

// WindowAttention3D: B_=4096, N=98 tok, C=96, H=3 heads, hd=32.
// R10: fully tensorized (mma.sync bf16 split hi/lo, fp32 accum):
// QKV GEMM -> tensor attention (S=QK^T, softmax in regs, PV with
// ones-column row-sums) -> proj GEMM. 1 CTA/window, 384 threads.

#define N_TOK 98
#define C_DIM 96
#define NHEAD 3
#define HD    32
#define NTHREADS 384
#define LDA   104

typedef unsigned long long u64;

// ---------------- helpers ----------------
__device__ __forceinline__ uint32_t smem_u32(const void* p) {
    uint32_t a;
    asm("{ .reg .u64 t; cvta.to.shared.u64 t, %1; cvt.u32.u64 %0, t; }"
        : "=r"(a) : "l"(p));
    return a;
}
__device__ __forceinline__ void ldsm4(uint32_t& r0, uint32_t& r1,
                                      uint32_t& r2, uint32_t& r3, uint32_t a) {
    asm volatile("ldmatrix.sync.aligned.m8n8.x4.shared.b16 {%0,%1,%2,%3}, [%4];"
                 : "=r"(r0), "=r"(r1), "=r"(r2), "=r"(r3) : "r"(a));
}
__device__ __forceinline__ void ldsm2(uint32_t& r0, uint32_t& r1, uint32_t a) {
    asm volatile("ldmatrix.sync.aligned.m8n8.x2.shared.b16 {%0,%1}, [%2];"
                 : "=r"(r0), "=r"(r1) : "r"(a));
}
__device__ __forceinline__ void mma16816(float* c, const uint32_t* a,
                                         const uint32_t* b) {
    asm volatile("mma.sync.aligned.m16n8k16.row.col.f32.bf16.bf16.f32 "
                 "{%0,%1,%2,%3}, {%4,%5,%6,%7}, {%8,%9}, {%0,%1,%2,%3};"
                 : "+f"(c[0]), "+f"(c[1]), "+f"(c[2]), "+f"(c[3])
                 : "r"(a[0]), "r"(a[1]), "r"(a[2]), "r"(a[3]),
                   "r"(b[0]), "r"(b[1]));
}
__device__ __forceinline__ void split_bf16(float f, __nv_bfloat16& h, __nv_bfloat16& l) {
    h = __float2bfloat16(f);
    l = __float2bfloat16(f - __bfloat162float(h));
}
__device__ __forceinline__ void st_bf162(char* p, __nv_bfloat16 a, __nv_bfloat16 b) {
    __nv_bfloat162 t; t.x = a; t.y = b;
    *reinterpret_cast<__nv_bfloat162*>(p) = t;
}

// swizzled byte offsets (c in bf16 elements)
// 64B-row arrays (q, k): 8 consecutive rows -> 8 distinct 16B slots mod 128.
__device__ __forceinline__ int sw_qk(int r, int c) {
    int off = r * 64 + c * 2;
    return off ^ (((r >> 1) & 3) << 4);
}
// 224B-row arrays (vt, P): rows r, r+4 disambiguated by bit-4 XOR.
__device__ __forceinline__ int sw_vtp(int r, int c) {
    int off = r * 224 + c * 2;
    return off ^ (((r >> 2) & 1) << 4);
}

// ---------------- smem map (bytes) ----------------
constexpr int A_BYTES = 112 * LDA * 2;                 // 23296
constexpr int SM_A_HI = 0;
constexpr int SM_A_LO = A_BYTES;                       // 23296
constexpr int SM_QH   = 2 * A_BYTES;                   // 46592
constexpr int QH_HEAD = 112 * 64;                      // 7168
constexpr int SM_QL   = SM_QH + 3 * QH_HEAD;           // 68096
constexpr int SM_KH   = SM_QL + 3 * QH_HEAD;           // 89600
constexpr int KH_HEAD = 104 * 64;                      // 6656
constexpr int SM_KL   = SM_KH + 3 * KH_HEAD;           // 109568
constexpr int SM_VTH  = SM_KL + 3 * KH_HEAD;           // 129536
constexpr int VT_HEAD = 40 * 224;                      // 8960
constexpr int SM_VTL  = SM_VTH + 3 * VT_HEAD;          // 156416
constexpr int SM_W    = SM_VTL + 3 * VT_HEAD;          // 183296
constexpr int WPANEL_BYTES = 96 * LDA * 2;             // 19968
constexpr int SM_WSL  = SM_W + WPANEL_BYTES;           // 203264
// attention-time overlays on W region:
constexpr int SM_PH   = SM_W;                          // 183296 (64 x 224)
constexpr int SM_PL   = SM_PH + 64 * 224;              // 197632
constexpr int SM_LSUM = SM_PL + 64 * 224;              // 211968 (64 floats)
constexpr int SM_OST  = SM_QH;                         // out staging (f32, 98x100)
constexpr int SMEM_BYTES = SM_WSL + WPANEL_BYTES;      // 223232

// ---------------- device globals ----------------
__device__ float g_bias[NHEAD * N_TOK * N_TOK];        // [h][r][m]
__device__ uint4 g_wq_hi4[288 * LDA * 2 / 16];
__device__ uint4 g_wq_lo4[288 * LDA * 2 / 16];
__device__ uint4 g_wp_hi4[96 * LDA * 2 / 16];
__device__ uint4 g_wp_lo4[96 * LDA * 2 / 16];

__global__ void bias_precompute_kernel(const float* __restrict__ table,
                                       const int* __restrict__ rel) {
    int idx = blockIdx.x * blockDim.x + threadIdx.x;
    if (idx >= NHEAD * N_TOK * N_TOK) return;
    int h   = idx / (N_TOK * N_TOK);
    int rem = idx - h * (N_TOK * N_TOK);
    int r   = rem / N_TOK;
    int m   = rem - r * N_TOK;
    g_bias[idx] = table[rel[r * N_TOK + m] * NHEAD + h];
}

__global__ void prep_w_kernel(const float* __restrict__ qkv_w,
                              const float* __restrict__ proj_w) {
    int idx = blockIdx.x * blockDim.x + threadIdx.x;
    const int QE = 288 * LDA;
    if (idx < QE) {
        int row = idx / LDA, col = idx - row * LDA;
        float v = (col < C_DIM) ? qkv_w[row * C_DIM + col] : 0.f;
        __nv_bfloat16 hi, lo; split_bf16(v, hi, lo);
        reinterpret_cast<__nv_bfloat16*>(g_wq_hi4)[idx] = hi;
        reinterpret_cast<__nv_bfloat16*>(g_wq_lo4)[idx] = lo;
    } else if (idx < QE + 96 * LDA) {
        int j = idx - QE;
        int row = j / LDA, col = j - row * LDA;
        float v = (col < C_DIM) ? proj_w[row * C_DIM + col] : 0.f;
        __nv_bfloat16 hi, lo; split_bf16(v, hi, lo);
        reinterpret_cast<__nv_bfloat16*>(g_wp_hi4)[j] = hi;
        reinterpret_cast<__nv_bfloat16*>(g_wp_lo4)[j] = lo;
    }
}

// ---------------- main kernel ----------------
__global__ __launch_bounds__(NTHREADS, 1)
void win_attn_mma(const float* __restrict__ x,
                  const float* __restrict__ qkv_b,
                  const float* __restrict__ proj_b,
                  float* __restrict__ out) {
    extern __shared__ char smc[];
    const uint32_t sb = smem_u32(smc);
    const int tid  = threadIdx.x;
    const int wid  = tid >> 5;
    const int lane = tid & 31;
    const long base = (long)blockIdx.x * (N_TOK * C_DIM);

    const int arow_l = (lane & 7) + ((lane >> 3) & 1) * 8;
    const int acol_l = (lane >> 4) * 8;
    const int l15    = lane & 15;
    const int brow_l = l15 & 7;
    const int bkh_l  = (l15 >> 3) * 8;

    // ---- zero A tiles + vt buffers ----
    {
        uint4 z = {0, 0, 0, 0};
        uint4* az = reinterpret_cast<uint4*>(smc + SM_A_HI);
        for (int i = tid; i < 2 * A_BYTES / 16; i += NTHREADS) az[i] = z;
        uint4* vz = reinterpret_cast<uint4*>(smc + SM_VTH);
        for (int i = tid; i < 6 * VT_HEAD / 16; i += NTHREADS) vz[i] = z;
    }
    __syncthreads();

    // ---- ones column (vt row d=32) + x split into A hi/lo ----
    for (int i = tid; i < NHEAD * N_TOK; i += NTHREADS) {
        int g = i / N_TOK, m = i - g * N_TOK;
        *reinterpret_cast<__nv_bfloat16*>(smc + SM_VTH + g * VT_HEAD + sw_vtp(32, m)) =
            __float2bfloat16(1.0f);
    }
    for (int i = tid; i < N_TOK * (C_DIM / 2); i += NTHREADS) {
        int row = i / (C_DIM / 2), cp = i - row * (C_DIM / 2);
        float2 v = *reinterpret_cast<const float2*>(x + base + row * C_DIM + cp * 2);
        __nv_bfloat16 h0, l0, h1, l1;
        split_bf16(v.x, h0, l0);  split_bf16(v.y, h1, l1);
        int off = (row * LDA + cp * 2) * 2;
        st_bf162(smc + SM_A_HI + off, h0, h1);
        st_bf162(smc + SM_A_LO + off, l0, l1);
    }

    // ---- Phase B: QKV GEMM, 3 passes (s = q, k, v) ----
    const float scale = 0.17677669529663687f;   // 1/sqrt(32)
    const int ng = wid % 6;
    const int mg = wid / 6;
    const int m_begin = mg * 4;
    const int m_end   = (mg == 0) ? 4 : 7;

    for (int s = 0; s < 3; s++) {
        __syncthreads();
        {
            const uint4* srcH = g_wq_hi4 + s * (WPANEL_BYTES / 16);
            const uint4* srcL = g_wq_lo4 + s * (WPANEL_BYTES / 16);
            uint4* dH = reinterpret_cast<uint4*>(smc + SM_W);
            uint4* dL = reinterpret_cast<uint4*>(smc + SM_WSL);
            for (int i = tid; i < WPANEL_BYTES / 16; i += NTHREADS) {
                dH[i] = srcH[i];  dL[i] = srcL[i];
            }
        }
        __syncthreads();

        uint32_t bh[2][6][2], bl[2][6][2];
        #pragma unroll
        for (int nt = 0; nt < 2; nt++) {
            int n0 = (2 * ng + nt) * 8;
            #pragma unroll
            for (int ksi = 0; ksi < 6; ksi++) {
                uint32_t off = (uint32_t)((n0 + brow_l) * LDA + ksi * 16 + bkh_l) * 2;
                ldsm2(bh[nt][ksi][0], bh[nt][ksi][1], sb + SM_W + off);
                ldsm2(bl[nt][ksi][0], bl[nt][ksi][1], sb + SM_WSL + off);
            }
        }

        for (int mt = m_begin; mt < m_end; mt++) {
            float acc[2][4] = {{0.f, 0.f, 0.f, 0.f}, {0.f, 0.f, 0.f, 0.f}};
            #pragma unroll
            for (int ksi = 0; ksi < 6; ksi++) {
                uint32_t offA = (uint32_t)((mt * 16 + arow_l) * LDA + ksi * 16 + acol_l) * 2;
                uint32_t ah[4], al[4];
                ldsm4(ah[0], ah[1], ah[2], ah[3], sb + SM_A_HI + offA);
                ldsm4(al[0], al[1], al[2], al[3], sb + SM_A_LO + offA);
                #pragma unroll
                for (int nt = 0; nt < 2; nt++) {
                    mma16816(acc[nt], ah, bh[nt][ksi]);
                    mma16816(acc[nt], ah, bl[nt][ksi]);
                    mma16816(acc[nt], al, bh[nt][ksi]);
                }
            }
            // epilogue -> bf16 hi/lo q / k / vt
            #pragma unroll
            for (int nt = 0; nt < 2; nt++) {
                int col = (2 * ng + nt) * 8 + (lane & 3) * 2;
                int hh = col >> 5, dd = col & 31;
                float b0 = __ldg(&qkv_b[s * C_DIM + col]);
                float b1 = __ldg(&qkv_b[s * C_DIM + col + 1]);
                float mul = (s == 0) ? scale : 1.0f;
                #pragma unroll
                for (int half = 0; half < 2; half++) {
                    int r = mt * 16 + (lane >> 2) + half * 8;
                    if (r >= N_TOK) continue;
                    float f0 = (acc[nt][2 * half + 0] + b0) * mul;
                    float f1 = (acc[nt][2 * half + 1] + b1) * mul;
                    __nv_bfloat16 h0, l0, h1, l1;
                    split_bf16(f0, h0, l0);  split_bf16(f1, h1, l1);
                    if (s == 0) {
                        int o = sw_qk(r, dd);
                        st_bf162(smc + SM_QH + hh * QH_HEAD + o, h0, h1);
                        st_bf162(smc + SM_QL + hh * QH_HEAD + o, l0, l1);
                    } else if (s == 1) {
                        int o = sw_qk(r, dd);
                        st_bf162(smc + SM_KH + hh * KH_HEAD + o, h0, h1);
                        st_bf162(smc + SM_KL + hh * KH_HEAD + o, l0, l1);
                    } else {
                        char* vh = smc + SM_VTH + hh * VT_HEAD;
                        char* vl = smc + SM_VTL + hh * VT_HEAD;
                        *reinterpret_cast<__nv_bfloat16*>(vh + sw_vtp(dd, r)) = h0;
                        *reinterpret_cast<__nv_bfloat16*>(vl + sw_vtp(dd, r)) = l0;
                        *reinterpret_cast<__nv_bfloat16*>(vh + sw_vtp(dd + 1, r)) = h1;
                        *reinterpret_cast<__nv_bfloat16*>(vl + sw_vtp(dd + 1, r)) = l1;
                    }
                }
            }
        }
    }
    __syncthreads();

    // ---- zero P cols 104..111 (bytes 208..223 of each row, both bufs) ----
    {
        uint4 z = {0, 0, 0, 0};
        for (int i = tid; i < 128; i += NTHREADS) {
            int r = i & 63, bsel = i >> 6;
            int off = sw_vtp(r, 104);     // 16B-aligned chunk at row end
            *reinterpret_cast<uint4*>(smc + (bsel ? SM_PL : SM_PH) + off) = z;
        }
    }

    // ---- Attention: per head, per row-group (m-tiles [0..3], [4..6]) ----
    for (int g = 0; g < NHEAD; g++) {
        const uint32_t qh = sb + SM_QH + g * QH_HEAD;
        const uint32_t ql = sb + SM_QL + g * QH_HEAD;
        const uint32_t kh = sb + SM_KH + g * KH_HEAD;
        const uint32_t kl = sb + SM_KL + g * KH_HEAD;
        const uint32_t vh = sb + SM_VTH + g * VT_HEAD;
        const uint32_t vl = sb + SM_VTL + g * VT_HEAD;
        const float* biasg = g_bias + g * (N_TOK * N_TOK);

        for (int grp = 0; grp < 2; grp++) {
            const int mt0  = (grp == 0) ? 0 : 4;
            const int nmt  = (grp == 0) ? 4 : 3;
            const int row0 = mt0 * 16;
            __syncthreads();   // P / lsum safe to overwrite

            // ---- S = Q K^T tiles + in-register softmax -> P (bf16 hi/lo) ----
            for (int t = wid; t < nmt * 13; t += 12) {
                int mt = mt0 + t / 13;
                int nt = t % 13;
                float acc[4] = {0.f, 0.f, 0.f, 0.f};
                #pragma unroll
                for (int ks = 0; ks < 2; ks++) {
                    uint32_t ah[4], al[4], bhf[2], blf[2];
                    int ao = sw_qk(mt * 16 + arow_l, ks * 16 + acol_l);
                    ldsm4(ah[0], ah[1], ah[2], ah[3], qh + ao);
                    ldsm4(al[0], al[1], al[2], al[3], ql + ao);
                    int bo = sw_qk(nt * 8 + brow_l, ks * 16 + bkh_l);
                    ldsm2(bhf[0], bhf[1], kh + bo);
                    ldsm2(blf[0], blf[1], kl + bo);
                    mma16816(acc, ah, bhf);
                    mma16816(acc, ah, blf);
                    mma16816(acc, al, bhf);
                }
                int m0 = nt * 8 + (lane & 3) * 2;
                #pragma unroll
                for (int half = 0; half < 2; half++) {
                    int r = mt * 16 + (lane >> 2) + half * 8;
                    float p0 = 0.f, p1 = 0.f;
                    if (r < N_TOK && m0 < N_TOK) {
                        float2 bv = __ldg(reinterpret_cast<const float2*>(
                            biasg + r * N_TOK + m0));
                        p0 = __expf(acc[2 * half + 0] + bv.x);
                        p1 = __expf(acc[2 * half + 1] + bv.y);
                    }
                    __nv_bfloat16 h0, l0, h1, l1;
                    split_bf16(p0, h0, l0);  split_bf16(p1, h1, l1);
                    int o = sw_vtp(r - row0, m0);
                    st_bf162(smc + SM_PH + o, h0, h1);
                    st_bf162(smc + SM_PL + o, l0, l1);
                }
            }
            __syncthreads();

            // ---- PV (+ ones column -> row sums) ----
            float pacc[2][4];
            int   ptile[2] = {-1, -1};
            int   np = 0;
            for (int t = wid; t < nmt * 5; t += 12) {
                int mtg = t / 5;          // m-tile within group
                int nt  = t % 5;          // d-tile (nt=4 -> cols 32..39, ones)
                float acc[4] = {0.f, 0.f, 0.f, 0.f};
                #pragma unroll
                for (int ks = 0; ks < 7; ks++) {
                    uint32_t ah[4], al[4], bhf[2], blf[2];
                    int ao = sw_vtp(mtg * 16 + arow_l, ks * 16 + acol_l);
                    ldsm4(ah[0], ah[1], ah[2], ah[3], sb + SM_PH + ao);
                    ldsm4(al[0], al[1], al[2], al[3], sb + SM_PL + ao);
                    int bo = sw_vtp(nt * 8 + brow_l, ks * 16 + bkh_l);
                    ldsm2(bhf[0], bhf[1], vh + bo);
                    ldsm2(blf[0], blf[1], vl + bo);
                    mma16816(acc, ah, bhf);
                    mma16816(acc, ah, blf);
                    mma16816(acc, al, bhf);
                }
                if (nt == 4) {
                    if ((lane & 3) == 0) {  // col 32 = sum(P) per row
                        float* ls = reinterpret_cast<float*>(smc + SM_LSUM);
                        int rg = mtg * 16 + (lane >> 2);
                        ls[rg]     = 1.0f / acc[0];
                        ls[rg + 8] = 1.0f / acc[2];
                    }
                } else {
                    pacc[np][0] = acc[0]; pacc[np][1] = acc[1];
                    pacc[np][2] = acc[2]; pacc[np][3] = acc[3];
                    ptile[np] = t; np++;
                }
            }
            __syncthreads();

            // ---- scale by 1/rowsum, store attn-out into A tiles (bf16 split) ----
            const float* ls = reinterpret_cast<const float*>(smc + SM_LSUM);
            for (int i = 0; i < np; i++) {
                int t = ptile[i];
                int mtg = t / 5, nt = t % 5;
                int d0 = nt * 8 + (lane & 3) * 2;
                #pragma unroll
                for (int half = 0; half < 2; half++) {
                    int rg = mtg * 16 + (lane >> 2) + half * 8;
                    int r = row0 + rg;
                    if (r >= N_TOK) continue;
                    float inv = ls[rg];
                    float f0 = pacc[i][2 * half + 0] * inv;
                    float f1 = pacc[i][2 * half + 1] * inv;
                    __nv_bfloat16 h0, l0, h1, l1;
                    split_bf16(f0, h0, l0);  split_bf16(f1, h1, l1);
                    int off = (r * LDA + g * HD + d0) * 2;
                    st_bf162(smc + SM_A_HI + off, h0, h1);
                    st_bf162(smc + SM_A_LO + off, l0, l1);
                }
            }
        }
    }
    __syncthreads();

    // ---- stage proj weights (overwrites P region; P dead) ----
    {
        uint4* dH = reinterpret_cast<uint4*>(smc + SM_W);
        uint4* dL = reinterpret_cast<uint4*>(smc + SM_WSL);
        for (int i = tid; i < WPANEL_BYTES / 16; i += NTHREADS) {
            dH[i] = g_wp_hi4[i];  dL[i] = g_wp_lo4[i];
        }
    }
    __syncthreads();

    // ---- proj GEMM: warp = n-tile (12), 7 m-tiles ----
    float* ost = reinterpret_cast<float*>(smc + SM_OST);
    {
        uint32_t bhf[6][2], blf[6][2];
        int n0 = wid * 8;
        #pragma unroll
        for (int ksi = 0; ksi < 6; ksi++) {
            uint32_t off = (uint32_t)((n0 + brow_l) * LDA + ksi * 16 + bkh_l) * 2;
            ldsm2(bhf[ksi][0], bhf[ksi][1], sb + SM_W + off);
            ldsm2(blf[ksi][0], blf[ksi][1], sb + SM_WSL + off);
        }
        int colb = n0 + (lane & 3) * 2;
        float b0 = __ldg(&proj_b[colb]);
        float b1 = __ldg(&proj_b[colb + 1]);
        for (int mt = 0; mt < 7; mt++) {
            float acc[4] = {0.f, 0.f, 0.f, 0.f};
            #pragma unroll
            for (int ksi = 0; ksi < 6; ksi++) {
                uint32_t offA = (uint32_t)((mt * 16 + arow_l) * LDA + ksi * 16 + acol_l) * 2;
                uint32_t ah[4], al[4];
                ldsm4(ah[0], ah[1], ah[2], ah[3], sb + SM_A_HI + offA);
                ldsm4(al[0], al[1], al[2], al[3], sb + SM_A_LO + offA);
                mma16816(acc, ah, bhf[ksi]);
                mma16816(acc, ah, blf[ksi]);
                mma16816(acc, al, bhf[ksi]);
            }
            int r0 = mt * 16 + (lane >> 2);
            if (r0 < N_TOK) {
                float2 v; v.x = acc[0] + b0; v.y = acc[1] + b1;
                *reinterpret_cast<float2*>(ost + r0 * 100 + colb) = v;
            }
            int r1 = r0 + 8;
            if (r1 < N_TOK) {
                float2 v; v.x = acc[2] + b0; v.y = acc[3] + b1;
                *reinterpret_cast<float2*>(ost + r1 * 100 + colb) = v;
            }
        }
    }
    __syncthreads();

    // ---- coalesced final store ----
    {
        float4* og = reinterpret_cast<float4*>(out + base);
        for (int i = tid; i < N_TOK * (C_DIM / 4); i += NTHREADS) {
            int row = i / (C_DIM / 4), q = i - row * (C_DIM / 4);
            og[i] = *reinterpret_cast<const float4*>(ost + row * 100 + 4 * q);
        }
    }
}

// ---------------- launch ----------------
extern "C" void kernel_launch(void* const* d_in, const int* in_sizes, int n_in,
                              void* d_out, int out_size) {
    const float* x      = (const float*)d_in[0];
    const float* qkv_w  = (const float*)d_in[1];
    const float* qkv_b  = (const float*)d_in[2];
    const float* proj_w = (const float*)d_in[3];
    const float* proj_b = (const float*)d_in[4];
    const float* table  = (const float*)d_in[5];
    const int*   rel    = (const int*)d_in[6];
    float* out = (float*)d_out;

    cudaFuncSetAttribute(win_attn_mma,
                         cudaFuncAttributeMaxDynamicSharedMemorySize, SMEM_BYTES);

    int nb = NHEAD * N_TOK * N_TOK;
    bias_precompute_kernel<<<(nb + 255) / 256, 256>>>(table, rel);
    int nw = 288 * LDA + 96 * LDA;
    prep_w_kernel<<<(nw + 255) / 256, 256>>>(qkv_w, proj_w);
    win_attn_mma<<<4096, NTHREADS, SMEM_BYTES>>>(x, qkv_b, proj_b, out);
}

// round 14
// speedup vs baseline: 1.0738x; 1.0738x over previous
#include <cuda_runtime.h>
#include <cuda_bf16.h>
#include <cstdint>

// WindowAttention3D: B_=4096, N=98 tok, C=96, H=3 heads, hd=32.
// R11: all-tensor (mma.sync bf16 split hi/lo x3, fp32 accum).
// QKV -> bf16 q/k/v directly; attention with per-head warp groups
// (named barriers), V row-major + ldmatrix.trans; proj GEMM.

#define N_TOK 98
#define C_DIM 96
#define NHEAD 3
#define NTHREADS 384

typedef unsigned long long u64;

// ---------------- helpers ----------------
__device__ __forceinline__ uint32_t smem_u32(const void* p) {
    uint32_t a;
    asm("{ .reg .u64 t; cvta.to.shared.u64 t, %1; cvt.u32.u64 %0, t; }"
        : "=r"(a) : "l"(p));
    return a;
}
__device__ __forceinline__ void ldsm4(uint32_t& r0, uint32_t& r1,
                                      uint32_t& r2, uint32_t& r3, uint32_t a) {
    asm volatile("ldmatrix.sync.aligned.m8n8.x4.shared.b16 {%0,%1,%2,%3}, [%4];"
                 : "=r"(r0), "=r"(r1), "=r"(r2), "=r"(r3) : "r"(a));
}
__device__ __forceinline__ void ldsm2(uint32_t& r0, uint32_t& r1, uint32_t a) {
    asm volatile("ldmatrix.sync.aligned.m8n8.x2.shared.b16 {%0,%1}, [%2];"
                 : "=r"(r0), "=r"(r1) : "r"(a));
}
__device__ __forceinline__ void ldsm2t(uint32_t& r0, uint32_t& r1, uint32_t a) {
    asm volatile("ldmatrix.sync.aligned.m8n8.x2.trans.shared.b16 {%0,%1}, [%2];"
                 : "=r"(r0), "=r"(r1) : "r"(a));
}
__device__ __forceinline__ void mma16816(float* c, const uint32_t* a,
                                         const uint32_t* b) {
    asm volatile("mma.sync.aligned.m16n8k16.row.col.f32.bf16.bf16.f32 "
                 "{%0,%1,%2,%3}, {%4,%5,%6,%7}, {%8,%9}, {%0,%1,%2,%3};"
                 : "+f"(c[0]), "+f"(c[1]), "+f"(c[2]), "+f"(c[3])
                 : "r"(a[0]), "r"(a[1]), "r"(a[2]), "r"(a[3]),
                   "r"(b[0]), "r"(b[1]));
}
__device__ __forceinline__ void split_bf16(float f, __nv_bfloat16& h, __nv_bfloat16& l) {
    h = __float2bfloat16(f);
    l = __float2bfloat16(f - __bfloat162float(h));
}
__device__ __forceinline__ void st_bf162(char* p, __nv_bfloat16 a, __nv_bfloat16 b) {
    __nv_bfloat162 t; t.x = a; t.y = b;
    *reinterpret_cast<__nv_bfloat162*>(p) = t;
}

// swizzled byte offsets (c = bf16 element column)
// A tiles: 96 cols, 192B rows; rows 0..7 -> distinct 16B slots.
__device__ __forceinline__ int swA(int r, int c) {
    return ((r * 96 + c) * 2) ^ (((r >> 1) & 3) << 4);
}
// q/k: 32 cols, 64B rows (R10-validated).
__device__ __forceinline__ int sw_qk(int r, int c) {
    return (r * 64 + c * 2) ^ (((r >> 1) & 3) << 4);
}
// P: 112 cols, 224B rows (R10-validated).
__device__ __forceinline__ int sw_p(int r, int c) {
    return (r * 224 + c * 2) ^ (((r >> 2) & 1) << 4);
}
// V: [m][40] bf16, 80B rows -> 8 consecutive rows conflict-free, no xor.

// ---------------- smem map (bytes) ----------------
constexpr int LDW = 104;                       // weight panel stride (bf16)
constexpr int SM_A_HI = 0;                     // 112 x 192B
constexpr int SM_A_LO = 21504;
constexpr int SM_QH   = 43008;                 // + g*7168 (112 x 64B)
constexpr int SM_QL   = 64512;
constexpr int SM_KH   = 86016;                 // + g*6656 (104 x 64B)
constexpr int SM_KL   = 105984;
constexpr int SM_VH   = 125952;                // + g*8960 (112 x 80B)
constexpr int SM_VL   = 152832;
constexpr int SM_W    = 179712;                // panel hi (96 x 208B)
constexpr int SM_WSL  = 199680;                // panel lo
constexpr int WPANEL_BYTES = 96 * LDW * 2;     // 19968
// attention overlay on W region: P per head = hi(7168)+lo(7168)
constexpr int SM_P    = SM_W;                  // + g*14336
constexpr int SM_LSUM = 222720;                // 96 floats
constexpr int SM_OST  = SM_QH;                 // f32 out staging 98x100
constexpr int SMEM_BYTES = 223232;

// ---------------- device globals ----------------
__device__ float g_bias[NHEAD * N_TOK * N_TOK];   // [h][r][m]
__device__ uint4 g_wq_hi4[288 * LDW * 2 / 16];
__device__ uint4 g_wq_lo4[288 * LDW * 2 / 16];
__device__ uint4 g_wp_hi4[96 * LDW * 2 / 16];
__device__ uint4 g_wp_lo4[96 * LDW * 2 / 16];

__global__ void bias_precompute_kernel(const float* __restrict__ table,
                                       const int* __restrict__ rel) {
    int idx = blockIdx.x * blockDim.x + threadIdx.x;
    if (idx >= NHEAD * N_TOK * N_TOK) return;
    int h   = idx / (N_TOK * N_TOK);
    int rem = idx - h * (N_TOK * N_TOK);
    int r   = rem / N_TOK;
    int m   = rem - r * N_TOK;
    g_bias[idx] = table[rel[r * N_TOK + m] * NHEAD + h];
}

__global__ void prep_w_kernel(const float* __restrict__ qkv_w,
                              const float* __restrict__ proj_w) {
    int idx = blockIdx.x * blockDim.x + threadIdx.x;
    const int QE = 288 * LDW;
    if (idx < QE) {
        int row = idx / LDW, col = idx - row * LDW;
        float v = (col < C_DIM) ? qkv_w[row * C_DIM + col] : 0.f;
        __nv_bfloat16 hi, lo; split_bf16(v, hi, lo);
        reinterpret_cast<__nv_bfloat16*>(g_wq_hi4)[idx] = hi;
        reinterpret_cast<__nv_bfloat16*>(g_wq_lo4)[idx] = lo;
    } else if (idx < QE + 96 * LDW) {
        int j = idx - QE;
        int row = j / LDW, col = j - row * LDW;
        float v = (col < C_DIM) ? proj_w[row * C_DIM + col] : 0.f;
        __nv_bfloat16 hi, lo; split_bf16(v, hi, lo);
        reinterpret_cast<__nv_bfloat16*>(g_wp_hi4)[j] = hi;
        reinterpret_cast<__nv_bfloat16*>(g_wp_lo4)[j] = lo;
    }
}

// ---------------- main kernel ----------------
__global__ __launch_bounds__(NTHREADS, 1)
void win_attn_mma(const float* __restrict__ x,
                  const float* __restrict__ qkv_b,
                  const float* __restrict__ proj_b,
                  float* __restrict__ out) {
    extern __shared__ char smc[];
    const uint32_t sb = smem_u32(smc);
    const int tid  = threadIdx.x;
    const int wid  = tid >> 5;
    const int lane = tid & 31;
    const long base = (long)blockIdx.x * (N_TOK * C_DIM);

    const int arow_l = (lane & 7) + ((lane >> 3) & 1) * 8;
    const int acol_l = (lane >> 4) * 8;
    const int l15    = lane & 15;
    const int brow_l = l15 & 7;
    const int bkh_l  = (l15 >> 3) * 8;

    // ---- zero V region (pads must be 0); split x -> A hi/lo ----
    {
        uint4 z = {0, 0, 0, 0};
        uint4* vz = reinterpret_cast<uint4*>(smc + SM_VH);
        for (int i = tid; i < 2 * 3 * 8960 / 16; i += NTHREADS) vz[i] = z;
    }
    for (int i = tid; i < N_TOK * (C_DIM / 2); i += NTHREADS) {
        int row = i / (C_DIM / 2), cp = i - row * (C_DIM / 2);
        float2 v = *reinterpret_cast<const float2*>(x + base + row * C_DIM + cp * 2);
        __nv_bfloat16 h0, l0, h1, l1;
        split_bf16(v.x, h0, l0);  split_bf16(v.y, h1, l1);
        int off = swA(row, cp * 2);
        st_bf162(smc + SM_A_HI + off, h0, h1);
        st_bf162(smc + SM_A_LO + off, l0, l1);
    }
    __syncthreads();
    // ones column of V (col 32, rows m<98) for softmax row-sums
    for (int i = tid; i < NHEAD * N_TOK; i += NTHREADS) {
        int g = i / N_TOK, m = i - g * N_TOK;
        *reinterpret_cast<__nv_bfloat16*>(smc + SM_VH + g * 8960 + (m * 40 + 32) * 2) =
            __float2bfloat16(1.0f);
    }

    // ---- Phase B: QKV GEMM, 3 passes (s = q, k, v) ----
    const float scale = 0.17677669529663687f;   // 1/sqrt(32)
    const int ng = wid % 6;
    const int mg = wid / 6;
    const int m_begin = mg * 4;
    const int m_end   = (mg == 0) ? 4 : 7;

    for (int s = 0; s < 3; s++) {
        __syncthreads();
        {
            const uint4* srcH = g_wq_hi4 + s * (WPANEL_BYTES / 16);
            const uint4* srcL = g_wq_lo4 + s * (WPANEL_BYTES / 16);
            uint4* dH = reinterpret_cast<uint4*>(smc + SM_W);
            uint4* dL = reinterpret_cast<uint4*>(smc + SM_WSL);
            for (int i = tid; i < WPANEL_BYTES / 16; i += NTHREADS) {
                dH[i] = srcH[i];  dL[i] = srcL[i];
            }
        }
        __syncthreads();

        uint32_t bh[2][6][2], bl[2][6][2];
        #pragma unroll
        for (int nt = 0; nt < 2; nt++) {
            int n0 = (2 * ng + nt) * 8;
            #pragma unroll
            for (int ksi = 0; ksi < 6; ksi++) {
                uint32_t off = (uint32_t)((n0 + brow_l) * LDW + ksi * 16 + bkh_l) * 2;
                ldsm2(bh[nt][ksi][0], bh[nt][ksi][1], sb + SM_W + off);
                ldsm2(bl[nt][ksi][0], bl[nt][ksi][1], sb + SM_WSL + off);
            }
        }

        for (int mt = m_begin; mt < m_end; mt++) {
            float acc[2][4] = {{0.f, 0.f, 0.f, 0.f}, {0.f, 0.f, 0.f, 0.f}};
            #pragma unroll
            for (int ksi = 0; ksi < 6; ksi++) {
                uint32_t offA = (uint32_t)swA(mt * 16 + arow_l, ksi * 16 + acol_l);
                uint32_t ah[4], al[4];
                ldsm4(ah[0], ah[1], ah[2], ah[3], sb + SM_A_HI + offA);
                ldsm4(al[0], al[1], al[2], al[3], sb + SM_A_LO + offA);
                #pragma unroll
                for (int nt = 0; nt < 2; nt++) {
                    mma16816(acc[nt], ah, bh[nt][ksi]);
                    mma16816(acc[nt], ah, bl[nt][ksi]);
                    mma16816(acc[nt], al, bh[nt][ksi]);
                }
            }
            // epilogue: bias (+scale for q) -> bf16 hi/lo q / k / v
            #pragma unroll
            for (int nt = 0; nt < 2; nt++) {
                int col = (2 * ng + nt) * 8 + (lane & 3) * 2;
                int hh = col >> 5, dd = col & 31;
                float b0 = __ldg(&qkv_b[s * C_DIM + col]);
                float b1 = __ldg(&qkv_b[s * C_DIM + col + 1]);
                float mul = (s == 0) ? scale : 1.0f;
                #pragma unroll
                for (int half = 0; half < 2; half++) {
                    int r = mt * 16 + (lane >> 2) + half * 8;
                    if (r >= N_TOK) continue;
                    float f0 = (acc[nt][2 * half + 0] + b0) * mul;
                    float f1 = (acc[nt][2 * half + 1] + b1) * mul;
                    __nv_bfloat16 h0, l0, h1, l1;
                    split_bf16(f0, h0, l0);  split_bf16(f1, h1, l1);
                    if (s == 0) {
                        int o = sw_qk(r, dd);
                        st_bf162(smc + SM_QH + hh * 7168 + o, h0, h1);
                        st_bf162(smc + SM_QL + hh * 7168 + o, l0, l1);
                    } else if (s == 1) {
                        int o = sw_qk(r, dd);
                        st_bf162(smc + SM_KH + hh * 6656 + o, h0, h1);
                        st_bf162(smc + SM_KL + hh * 6656 + o, l0, l1);
                    } else {
                        int o = (r * 40 + dd) * 2;   // row-major V, no swizzle
                        st_bf162(smc + SM_VH + hh * 8960 + o, h0, h1);
                        st_bf162(smc + SM_VL + hh * 8960 + o, l0, l1);
                    }
                }
            }
        }
    }
    __syncthreads();

    // ---- zero P pad cols 104..111 (both bufs, 3 heads, 32 rows) ----
    {
        uint4 z = {0, 0, 0, 0};
        for (int i = tid; i < 192; i += NTHREADS) {
            int g = i / 64, rb = i - g * 64;
            int bsel = rb >> 5, r = rb & 31;
            int off = sw_p(r, 104);
            *reinterpret_cast<uint4*>(smc + SM_P + g * 14336 + bsel * 7168 + off) = z;
        }
    }
    __syncthreads();

    // ---- Attention: 4 warps per head, named barriers, 4 row-groups ----
    {
        const int g    = wid >> 2;
        const int subw = wid & 3;
        const uint32_t qhB = sb + SM_QH + g * 7168;
        const uint32_t qlB = sb + SM_QL + g * 7168;
        const uint32_t khB = sb + SM_KH + g * 6656;
        const uint32_t klB = sb + SM_KL + g * 6656;
        const uint32_t vhB = sb + SM_VH + g * 8960;
        const uint32_t vlB = sb + SM_VL + g * 8960;
        char* pH = smc + SM_P + g * 14336;
        char* pL = pH + 7168;
        const uint32_t pHs = sb + SM_P + g * 14336;
        const uint32_t pLs = pHs + 7168;
        float* ls = reinterpret_cast<float*>(smc + SM_LSUM) + g * 32;
        const float* biasg = g_bias + g * (N_TOK * N_TOK);

        for (int grp = 0; grp < 4; grp++) {
            const int nmt  = (grp < 3) ? 2 : 1;
            const int mt0  = 2 * grp;
            const int row0 = 32 * grp;

            // ---- S = Q K^T -> softmax numerators into P (bf16 hi/lo) ----
            for (int t = subw; t < nmt * 13; t += 4) {
                int mt = mt0 + t / 13;
                int nt = t % 13;
                float acc[4] = {0.f, 0.f, 0.f, 0.f};
                #pragma unroll
                for (int ks = 0; ks < 2; ks++) {
                    uint32_t ah[4], al[4], bhf[2], blf[2];
                    int ao = sw_qk(mt * 16 + arow_l, ks * 16 + acol_l);
                    ldsm4(ah[0], ah[1], ah[2], ah[3], qhB + ao);
                    ldsm4(al[0], al[1], al[2], al[3], qlB + ao);
                    int bo = sw_qk(nt * 8 + brow_l, ks * 16 + bkh_l);
                    ldsm2(bhf[0], bhf[1], khB + bo);
                    ldsm2(blf[0], blf[1], klB + bo);
                    mma16816(acc, ah, bhf);
                    mma16816(acc, ah, blf);
                    mma16816(acc, al, bhf);
                }
                int m0 = nt * 8 + (lane & 3) * 2;
                #pragma unroll
                for (int half = 0; half < 2; half++) {
                    int r = mt * 16 + (lane >> 2) + half * 8;
                    float p0 = 0.f, p1 = 0.f;
                    if (r < N_TOK && m0 < N_TOK) {
                        float2 bv = __ldg(reinterpret_cast<const float2*>(
                            biasg + r * N_TOK + m0));
                        p0 = __expf(acc[2 * half + 0] + bv.x);
                        p1 = __expf(acc[2 * half + 1] + bv.y);
                    }
                    __nv_bfloat16 h0, l0, h1, l1;
                    split_bf16(p0, h0, l0);  split_bf16(p1, h1, l1);
                    int o = sw_p(r - row0, m0);
                    st_bf162(pH + o, h0, h1);
                    st_bf162(pL + o, l0, l1);
                }
            }
            asm volatile("bar.sync %0, %1;" :: "r"(g + 1), "r"(128) : "memory");

            // ---- PV (V row-major via ldmatrix.trans; nt=4 = ones -> rowsum) ----
            float pacc[3][4];
            int   ptile[3];
            int   np = 0;
            for (int t = subw; t < nmt * 5; t += 4) {
                int mtg = t / 5;
                int nt  = t % 5;
                float acc[4] = {0.f, 0.f, 0.f, 0.f};
                #pragma unroll
                for (int ks = 0; ks < 7; ks++) {
                    uint32_t ah[4], al[4], bhf[2], blf[2];
                    int ao = sw_p(mtg * 16 + arow_l, ks * 16 + acol_l);
                    ldsm4(ah[0], ah[1], ah[2], ah[3], pHs + ao);
                    ldsm4(al[0], al[1], al[2], al[3], pLs + ao);
                    uint32_t bo = (uint32_t)((ks * 16 + l15) * 40 + nt * 8) * 2;
                    ldsm2t(bhf[0], bhf[1], vhB + bo);
                    ldsm2t(blf[0], blf[1], vlB + bo);
                    mma16816(acc, ah, bhf);
                    mma16816(acc, ah, blf);
                    mma16816(acc, al, bhf);
                }
                if (nt == 4) {
                    if ((lane & 3) == 0) {        // col 32 = row sum of P
                        int rg = mtg * 16 + (lane >> 2);
                        ls[rg]     = 1.0f / acc[0];
                        ls[rg + 8] = 1.0f / acc[2];
                    }
                } else {
                    pacc[np][0] = acc[0]; pacc[np][1] = acc[1];
                    pacc[np][2] = acc[2]; pacc[np][3] = acc[3];
                    ptile[np] = t; np++;
                }
            }
            asm volatile("bar.sync %0, %1;" :: "r"(g + 1), "r"(128) : "memory");

            // ---- scale by 1/rowsum, store attn-out into A tiles (bf16 split) ----
            for (int i = 0; i < np; i++) {
                int t = ptile[i];
                int mtg = t / 5, nt = t % 5;
                int d0 = nt * 8 + (lane & 3) * 2;
                #pragma unroll
                for (int half = 0; half < 2; half++) {
                    int rg = mtg * 16 + (lane >> 2) + half * 8;
                    int r = row0 + rg;
                    if (r >= N_TOK) continue;
                    float inv = ls[rg];
                    float f0 = pacc[i][2 * half + 0] * inv;
                    float f1 = pacc[i][2 * half + 1] * inv;
                    __nv_bfloat16 h0, l0, h1, l1;
                    split_bf16(f0, h0, l0);  split_bf16(f1, h1, l1);
                    int off = swA(r, g * 32 + d0);
                    st_bf162(smc + SM_A_HI + off, h0, h1);
                    st_bf162(smc + SM_A_LO + off, l0, l1);
                }
            }
        }
    }
    __syncthreads();

    // ---- stage proj weights (P dead) ----
    {
        uint4* dH = reinterpret_cast<uint4*>(smc + SM_W);
        uint4* dL = reinterpret_cast<uint4*>(smc + SM_WSL);
        for (int i = tid; i < WPANEL_BYTES / 16; i += NTHREADS) {
            dH[i] = g_wp_hi4[i];  dL[i] = g_wp_lo4[i];
        }
    }
    __syncthreads();

    // ---- proj GEMM: warp = n-tile (12), 7 m-tiles ----
    float* ost = reinterpret_cast<float*>(smc + SM_OST);
    {
        uint32_t bhf[6][2], blf[6][2];
        int n0 = wid * 8;
        #pragma unroll
        for (int ksi = 0; ksi < 6; ksi++) {
            uint32_t off = (uint32_t)((n0 + brow_l) * LDW + ksi * 16 + bkh_l) * 2;
            ldsm2(bhf[ksi][0], bhf[ksi][1], sb + SM_W + off);
            ldsm2(blf[ksi][0], blf[ksi][1], sb + SM_WSL + off);
        }
        int colb = n0 + (lane & 3) * 2;
        float b0 = __ldg(&proj_b[colb]);
        float b1 = __ldg(&proj_b[colb + 1]);
        for (int mt = 0; mt < 7; mt++) {
            float acc[4] = {0.f, 0.f, 0.f, 0.f};
            #pragma unroll
            for (int ksi = 0; ksi < 6; ksi++) {
                uint32_t offA = (uint32_t)swA(mt * 16 + arow_l, ksi * 16 + acol_l);
                uint32_t ah[4], al[4];
                ldsm4(ah[0], ah[1], ah[2], ah[3], sb + SM_A_HI + offA);
                ldsm4(al[0], al[1], al[2], al[3], sb + SM_A_LO + offA);
                mma16816(acc, ah, bhf[ksi]);
                mma16816(acc, ah, blf[ksi]);
                mma16816(acc, al, bhf[ksi]);
            }
            int r0 = mt * 16 + (lane >> 2);
            if (r0 < N_TOK) {
                float2 v; v.x = acc[0] + b0; v.y = acc[1] + b1;
                *reinterpret_cast<float2*>(ost + r0 * 100 + colb) = v;
            }
            int r1 = r0 + 8;
            if (r1 < N_TOK) {
                float2 v; v.x = acc[2] + b0; v.y = acc[3] + b1;
                *reinterpret_cast<float2*>(ost + r1 * 100 + colb) = v;
            }
        }
    }
    __syncthreads();

    // ---- coalesced final store ----
    {
        float4* og = reinterpret_cast<float4*>(out + base);
        for (int i = tid; i < N_TOK * (C_DIM / 4); i += NTHREADS) {
            int row = i / (C_DIM / 4), q = i - row * (C_DIM / 4);
            og[i] = *reinterpret_cast<const float4*>(ost + row * 100 + 4 * q);
        }
    }
}

// ---------------- launch ----------------
extern "C" void kernel_launch(void* const* d_in, const int* in_sizes, int n_in,
                              void* d_out, int out_size) {
    const float* x      = (const float*)d_in[0];
    const float* qkv_w  = (const float*)d_in[1];
    const float* qkv_b  = (const float*)d_in[2];
    const float* proj_w = (const float*)d_in[3];
    const float* proj_b = (const float*)d_in[4];
    const float* table  = (const float*)d_in[5];
    const int*   rel    = (const int*)d_in[6];
    float* out = (float*)d_out;

    cudaFuncSetAttribute(win_attn_mma,
                         cudaFuncAttributeMaxDynamicSharedMemorySize, SMEM_BYTES);

    int nb = NHEAD * N_TOK * N_TOK;
    bias_precompute_kernel<<<(nb + 255) / 256, 256>>>(table, rel);
    int nw = 288 * LDW + 96 * LDW;
    prep_w_kernel<<<(nw + 255) / 256, 256>>>(qkv_w, proj_w);
    win_attn_mma<<<4096, NTHREADS, SMEM_BYTES>>>(x, qkv_b, proj_b, out);
}

// round 15
// speedup vs baseline: 1.1077x; 1.0316x over previous
#include <cuda_runtime.h>
#include <cuda_bf16.h>
#include <cstdint>

// WindowAttention3D: B_=4096, N=98 tok, C=96, H=3 heads, hd=32.
// R15: all-tensor mma.sync bf16 (split hi/lo x3, fp32 accum).
// Weight B-fragments loaded DIRECTLY from gmem (CTA-invariant, documented
// mma fragment layout) -> no weight smem staging, minimal syncs.

#define N_TOK 98
#define C_DIM 96
#define NHEAD 3
#define NTHREADS 384

typedef unsigned long long u64;

// ---------------- helpers ----------------
__device__ __forceinline__ uint32_t smem_u32(const void* p) {
    uint32_t a;
    asm("{ .reg .u64 t; cvta.to.shared.u64 t, %1; cvt.u32.u64 %0, t; }"
        : "=r"(a) : "l"(p));
    return a;
}
__device__ __forceinline__ void ldsm4(uint32_t& r0, uint32_t& r1,
                                      uint32_t& r2, uint32_t& r3, uint32_t a) {
    asm volatile("ldmatrix.sync.aligned.m8n8.x4.shared.b16 {%0,%1,%2,%3}, [%4];"
                 : "=r"(r0), "=r"(r1), "=r"(r2), "=r"(r3) : "r"(a));
}
__device__ __forceinline__ void ldsm2(uint32_t& r0, uint32_t& r1, uint32_t a) {
    asm volatile("ldmatrix.sync.aligned.m8n8.x2.shared.b16 {%0,%1}, [%2];"
                 : "=r"(r0), "=r"(r1) : "r"(a));
}
__device__ __forceinline__ void ldsm2t(uint32_t& r0, uint32_t& r1, uint32_t a) {
    asm volatile("ldmatrix.sync.aligned.m8n8.x2.trans.shared.b16 {%0,%1}, [%2];"
                 : "=r"(r0), "=r"(r1) : "r"(a));
}
__device__ __forceinline__ void mma16816(float* c, const uint32_t* a,
                                         const uint32_t* b) {
    asm volatile("mma.sync.aligned.m16n8k16.row.col.f32.bf16.bf16.f32 "
                 "{%0,%1,%2,%3}, {%4,%5,%6,%7}, {%8,%9}, {%0,%1,%2,%3};"
                 : "+f"(c[0]), "+f"(c[1]), "+f"(c[2]), "+f"(c[3])
                 : "r"(a[0]), "r"(a[1]), "r"(a[2]), "r"(a[3]),
                   "r"(b[0]), "r"(b[1]));
}
__device__ __forceinline__ void split_bf16(float f, __nv_bfloat16& h, __nv_bfloat16& l) {
    h = __float2bfloat16(f);
    l = __float2bfloat16(f - __bfloat162float(h));
}
__device__ __forceinline__ void st_bf162(char* p, __nv_bfloat16 a, __nv_bfloat16 b) {
    __nv_bfloat162 t; t.x = a; t.y = b;
    *reinterpret_cast<__nv_bfloat162*>(p) = t;
}

// swizzled byte offsets (c = bf16 element column)
__device__ __forceinline__ int swA(int r, int c) {          // A: 192B rows
    return ((r * 96 + c) * 2) ^ (((r >> 1) & 3) << 4);
}
__device__ __forceinline__ int sw_qk(int r, int c) {        // q/k: 64B rows
    return (r * 64 + c * 2) ^ (((r >> 1) & 3) << 4);
}
__device__ __forceinline__ int sw_p(int r, int c) {         // P: 224B rows
    return (r * 224 + c * 2) ^ (((r >> 2) & 1) << 4);
}
// V: [m][40] bf16, 80B rows, no xor needed.

// ---------------- smem map (bytes) ----------------
constexpr int SM_A_HI = 0;                     // 112 x 192B
constexpr int SM_A_LO = 21504;
constexpr int SM_QH   = 43008;                 // + g*7168 (112 x 64B)
constexpr int SM_QL   = 64512;
constexpr int SM_KH   = 86016;                 // + g*6656 (104 x 64B)
constexpr int SM_KL   = 105984;
constexpr int SM_VH   = 125952;                // + g*8960 (112 x 80B)
constexpr int SM_VL   = 152832;
constexpr int SM_P    = 179712;                // + g*14336 (hi 7168 | lo 7168)
constexpr int SM_LSUM = 222720;                // 96 floats
constexpr int SM_OST  = SM_QH;                 // f32 out staging 98x100
constexpr int SMEM_BYTES = 223104;

// ---------------- device globals ----------------
__device__ float g_bias[NHEAD * N_TOK * N_TOK];        // [h][r][m]
__device__ __nv_bfloat16 g_wq_hi[288 * 96];            // row-major [n][k]
__device__ __nv_bfloat16 g_wq_lo[288 * 96];
__device__ __nv_bfloat16 g_wp_hi[96 * 96];
__device__ __nv_bfloat16 g_wp_lo[96 * 96];

__global__ void prep_all_kernel(const float* __restrict__ qkv_w,
                                const float* __restrict__ proj_w,
                                const float* __restrict__ table,
                                const int* __restrict__ rel) {
    int idx = blockIdx.x * blockDim.x + threadIdx.x;
    const int QE = 288 * 96, PE = 96 * 96;
    if (idx < QE) {
        float v = qkv_w[idx];
        __nv_bfloat16 hi, lo; split_bf16(v, hi, lo);
        g_wq_hi[idx] = hi;  g_wq_lo[idx] = lo;
    } else if (idx < QE + PE) {
        float v = proj_w[idx - QE];
        __nv_bfloat16 hi, lo; split_bf16(v, hi, lo);
        g_wp_hi[idx - QE] = hi;  g_wp_lo[idx - QE] = lo;
    } else if (idx < QE + PE + NHEAD * N_TOK * N_TOK) {
        int j = idx - QE - PE;
        int h   = j / (N_TOK * N_TOK);
        int rem = j - h * (N_TOK * N_TOK);
        int r   = rem / N_TOK;
        int m   = rem - r * N_TOK;
        g_bias[j] = table[rel[r * N_TOK + m] * NHEAD + h];
    }
}

// ---------------- main kernel ----------------
__global__ __launch_bounds__(NTHREADS, 1)
void win_attn_mma(const float* __restrict__ x,
                  const float* __restrict__ qkv_b,
                  const float* __restrict__ proj_b,
                  float* __restrict__ out) {
    extern __shared__ char smc[];
    const uint32_t sb = smem_u32(smc);
    const int tid  = threadIdx.x;
    const int wid  = tid >> 5;
    const int lane = tid & 31;
    const long base = (long)blockIdx.x * (N_TOK * C_DIM);

    const int arow_l = (lane & 7) + ((lane >> 3) & 1) * 8;
    const int acol_l = (lane >> 4) * 8;
    const int l15    = lane & 31 & 15;
    const int nrow_l = lane >> 2;          // B-frag n offset (0..7)
    const int kk_l   = (lane & 3) * 2;     // B-frag k offset

    // ---- zero V region; P pad cols; split x -> A hi/lo; ones col ----
    {
        uint4 z = {0, 0, 0, 0};
        uint4* vz = reinterpret_cast<uint4*>(smc + SM_VH);
        for (int i = tid; i < 2 * 3 * 8960 / 16; i += NTHREADS) vz[i] = z;
        // P pad cols 104..111, 3 heads x (hi,lo) x 32 rows
        for (int i = tid; i < 192; i += NTHREADS) {
            int g = i / 64, rb = i - g * 64;
            int bsel = rb >> 5, r = rb & 31;
            *reinterpret_cast<uint4*>(smc + SM_P + g * 14336 + bsel * 7168
                                      + sw_p(r, 104)) = z;
        }
    }
    for (int i = tid; i < N_TOK * (C_DIM / 2); i += NTHREADS) {
        int row = i / (C_DIM / 2), cp = i - row * (C_DIM / 2);
        float2 v = *reinterpret_cast<const float2*>(x + base + row * C_DIM + cp * 2);
        __nv_bfloat16 h0, l0, h1, l1;
        split_bf16(v.x, h0, l0);  split_bf16(v.y, h1, l1);
        int off = swA(row, cp * 2);
        st_bf162(smc + SM_A_HI + off, h0, h1);
        st_bf162(smc + SM_A_LO + off, l0, l1);
    }
    __syncthreads();
    for (int i = tid; i < NHEAD * N_TOK; i += NTHREADS) {
        int g = i / N_TOK, m = i - g * N_TOK;
        *reinterpret_cast<__nv_bfloat16*>(smc + SM_VH + g * 8960 + (m * 40 + 32) * 2) =
            __float2bfloat16(1.0f);
    }

    // ---- Phase B: QKV GEMM, 3 passes; B-frags DIRECT from gmem ----
    const float scale = 0.17677669529663687f;   // 1/sqrt(32)
    const int ng = wid % 6;
    const int mg = wid / 6;
    const int m_begin = mg * 4;
    const int m_end   = (mg == 0) ? 4 : 7;

    #pragma unroll 1
    for (int s = 0; s < 3; s++) {
        uint32_t bh[2][6][2], bl[2][6][2];
        #pragma unroll
        for (int nt = 0; nt < 2; nt++) {
            int n = (2 * ng + nt) * 8 + nrow_l;
            const __nv_bfloat16* WH = g_wq_hi + (s * 96 + n) * 96;
            const __nv_bfloat16* WL = g_wq_lo + (s * 96 + n) * 96;
            #pragma unroll
            for (int ks = 0; ks < 6; ks++) {
                bh[nt][ks][0] = __ldg(reinterpret_cast<const uint32_t*>(WH + ks * 16 + kk_l));
                bh[nt][ks][1] = __ldg(reinterpret_cast<const uint32_t*>(WH + ks * 16 + kk_l + 8));
                bl[nt][ks][0] = __ldg(reinterpret_cast<const uint32_t*>(WL + ks * 16 + kk_l));
                bl[nt][ks][1] = __ldg(reinterpret_cast<const uint32_t*>(WL + ks * 16 + kk_l + 8));
            }
        }
        for (int mt = m_begin; mt < m_end; mt++) {
            float acc[2][4] = {{0.f, 0.f, 0.f, 0.f}, {0.f, 0.f, 0.f, 0.f}};
            #pragma unroll
            for (int ksi = 0; ksi < 6; ksi++) {
                uint32_t offA = (uint32_t)swA(mt * 16 + arow_l, ksi * 16 + acol_l);
                uint32_t ah[4], al[4];
                ldsm4(ah[0], ah[1], ah[2], ah[3], sb + SM_A_HI + offA);
                ldsm4(al[0], al[1], al[2], al[3], sb + SM_A_LO + offA);
                #pragma unroll
                for (int nt = 0; nt < 2; nt++) {
                    mma16816(acc[nt], ah, bh[nt][ksi]);
                    mma16816(acc[nt], ah, bl[nt][ksi]);
                    mma16816(acc[nt], al, bh[nt][ksi]);
                }
            }
            #pragma unroll
            for (int nt = 0; nt < 2; nt++) {
                int col = (2 * ng + nt) * 8 + kk_l;
                int hh = col >> 5, dd = col & 31;
                float b0 = __ldg(&qkv_b[s * C_DIM + col]);
                float b1 = __ldg(&qkv_b[s * C_DIM + col + 1]);
                float mul = (s == 0) ? scale : 1.0f;
                #pragma unroll
                for (int half = 0; half < 2; half++) {
                    int r = mt * 16 + nrow_l + half * 8;
                    if (r >= N_TOK) continue;
                    float f0 = (acc[nt][2 * half + 0] + b0) * mul;
                    float f1 = (acc[nt][2 * half + 1] + b1) * mul;
                    __nv_bfloat16 h0, l0, h1, l1;
                    split_bf16(f0, h0, l0);  split_bf16(f1, h1, l1);
                    if (s == 0) {
                        int o = sw_qk(r, dd);
                        st_bf162(smc + SM_QH + hh * 7168 + o, h0, h1);
                        st_bf162(smc + SM_QL + hh * 7168 + o, l0, l1);
                    } else if (s == 1) {
                        int o = sw_qk(r, dd);
                        st_bf162(smc + SM_KH + hh * 6656 + o, h0, h1);
                        st_bf162(smc + SM_KL + hh * 6656 + o, l0, l1);
                    } else {
                        int o = (r * 40 + dd) * 2;
                        st_bf162(smc + SM_VH + hh * 8960 + o, h0, h1);
                        st_bf162(smc + SM_VL + hh * 8960 + o, l0, l1);
                    }
                }
            }
        }
    }
    __syncthreads();

    // ---- Attention: 4 warps per head, named barriers, 4 row-groups ----
    {
        const int g    = wid >> 2;
        const int subw = wid & 3;
        const uint32_t qhB = sb + SM_QH + g * 7168;
        const uint32_t qlB = sb + SM_QL + g * 7168;
        const uint32_t khB = sb + SM_KH + g * 6656;
        const uint32_t klB = sb + SM_KL + g * 6656;
        const uint32_t vhB = sb + SM_VH + g * 8960;
        const uint32_t vlB = sb + SM_VL + g * 8960;
        char* pH = smc + SM_P + g * 14336;
        char* pL = pH + 7168;
        const uint32_t pHs = sb + SM_P + g * 14336;
        const uint32_t pLs = pHs + 7168;
        float* ls = reinterpret_cast<float*>(smc + SM_LSUM) + g * 32;
        const float* biasg = g_bias + g * (N_TOK * N_TOK);

        for (int grp = 0; grp < 4; grp++) {
            const int nmt  = (grp < 3) ? 2 : 1;
            const int mt0  = 2 * grp;
            const int row0 = 32 * grp;

            // S = Q K^T -> exp(S+bias) into P (bf16 hi/lo)
            for (int t = subw; t < nmt * 13; t += 4) {
                int mt = mt0 + t / 13;
                int nt = t % 13;
                float acc[4] = {0.f, 0.f, 0.f, 0.f};
                #pragma unroll
                for (int ks = 0; ks < 2; ks++) {
                    uint32_t ah[4], al[4], bhf[2], blf[2];
                    int ao = sw_qk(mt * 16 + arow_l, ks * 16 + acol_l);
                    ldsm4(ah[0], ah[1], ah[2], ah[3], qhB + ao);
                    ldsm4(al[0], al[1], al[2], al[3], qlB + ao);
                    int bo = sw_qk(nt * 8 + (l15 & 7), ks * 16 + (l15 >> 3) * 8);
                    ldsm2(bhf[0], bhf[1], khB + bo);
                    ldsm2(blf[0], blf[1], klB + bo);
                    mma16816(acc, ah, bhf);
                    mma16816(acc, ah, blf);
                    mma16816(acc, al, bhf);
                }
                int m0 = nt * 8 + kk_l;
                #pragma unroll
                for (int half = 0; half < 2; half++) {
                    int r = mt * 16 + nrow_l + half * 8;
                    float p0 = 0.f, p1 = 0.f;
                    if (r < N_TOK && m0 < N_TOK) {
                        float2 bv = __ldg(reinterpret_cast<const float2*>(
                            biasg + r * N_TOK + m0));
                        p0 = __expf(acc[2 * half + 0] + bv.x);
                        p1 = __expf(acc[2 * half + 1] + bv.y);
                    }
                    __nv_bfloat16 h0, l0, h1, l1;
                    split_bf16(p0, h0, l0);  split_bf16(p1, h1, l1);
                    int o = sw_p(r - row0, m0);
                    st_bf162(pH + o, h0, h1);
                    st_bf162(pL + o, l0, l1);
                }
            }
            asm volatile("bar.sync %0, %1;" :: "r"(g + 1), "r"(128) : "memory");

            // PV (V row-major via ldmatrix.trans; nt=4 = ones col -> rowsum)
            float pacc[3][4];
            int   ptile[3];
            int   np = 0;
            for (int t = subw; t < nmt * 5; t += 4) {
                int mtg = t / 5;
                int nt  = t % 5;
                float acc[4] = {0.f, 0.f, 0.f, 0.f};
                #pragma unroll
                for (int ks = 0; ks < 7; ks++) {
                    uint32_t ah[4], al[4], bhf[2], blf[2];
                    int ao = sw_p(mtg * 16 + arow_l, ks * 16 + acol_l);
                    ldsm4(ah[0], ah[1], ah[2], ah[3], pHs + ao);
                    ldsm4(al[0], al[1], al[2], al[3], pLs + ao);
                    uint32_t bo = (uint32_t)((ks * 16 + l15) * 40 + nt * 8) * 2;
                    ldsm2t(bhf[0], bhf[1], vhB + bo);
                    ldsm2t(blf[0], blf[1], vlB + bo);
                    mma16816(acc, ah, bhf);
                    mma16816(acc, ah, blf);
                    mma16816(acc, al, bhf);
                }
                if (nt == 4) {
                    if ((lane & 3) == 0) {
                        int rg = mtg * 16 + nrow_l;
                        ls[rg]     = 1.0f / acc[0];
                        ls[rg + 8] = 1.0f / acc[2];
                    }
                } else {
                    pacc[np][0] = acc[0]; pacc[np][1] = acc[1];
                    pacc[np][2] = acc[2]; pacc[np][3] = acc[3];
                    ptile[np] = t; np++;
                }
            }
            asm volatile("bar.sync %0, %1;" :: "r"(g + 1), "r"(128) : "memory");

            // scale by 1/rowsum -> A tiles (bf16 split)
            for (int i = 0; i < np; i++) {
                int t = ptile[i];
                int mtg = t / 5, nt = t % 5;
                int d0 = nt * 8 + kk_l;
                #pragma unroll
                for (int half = 0; half < 2; half++) {
                    int rg = mtg * 16 + nrow_l + half * 8;
                    int r = row0 + rg;
                    if (r >= N_TOK) continue;
                    float inv = ls[rg];
                    float f0 = pacc[i][2 * half + 0] * inv;
                    float f1 = pacc[i][2 * half + 1] * inv;
                    __nv_bfloat16 h0, l0, h1, l1;
                    split_bf16(f0, h0, l0);  split_bf16(f1, h1, l1);
                    int off = swA(r, g * 32 + d0);
                    st_bf162(smc + SM_A_HI + off, h0, h1);
                    st_bf162(smc + SM_A_LO + off, l0, l1);
                }
            }
        }
    }
    __syncthreads();

    // ---- proj GEMM: warp = n-tile (12), 7 m-tiles; B-frags from gmem ----
    float* ost = reinterpret_cast<float*>(smc + SM_OST);
    {
        uint32_t bhf[6][2], blf[6][2];
        {
            int n = wid * 8 + nrow_l;
            const __nv_bfloat16* WH = g_wp_hi + n * 96;
            const __nv_bfloat16* WL = g_wp_lo + n * 96;
            #pragma unroll
            for (int ks = 0; ks < 6; ks++) {
                bhf[ks][0] = __ldg(reinterpret_cast<const uint32_t*>(WH + ks * 16 + kk_l));
                bhf[ks][1] = __ldg(reinterpret_cast<const uint32_t*>(WH + ks * 16 + kk_l + 8));
                blf[ks][0] = __ldg(reinterpret_cast<const uint32_t*>(WL + ks * 16 + kk_l));
                blf[ks][1] = __ldg(reinterpret_cast<const uint32_t*>(WL + ks * 16 + kk_l + 8));
            }
        }
        int colb = wid * 8 + kk_l;
        float b0 = __ldg(&proj_b[colb]);
        float b1 = __ldg(&proj_b[colb + 1]);
        for (int mt = 0; mt < 7; mt++) {
            float acc[4] = {0.f, 0.f, 0.f, 0.f};
            #pragma unroll
            for (int ksi = 0; ksi < 6; ksi++) {
                uint32_t offA = (uint32_t)swA(mt * 16 + arow_l, ksi * 16 + acol_l);
                uint32_t ah[4], al[4];
                ldsm4(ah[0], ah[1], ah[2], ah[3], sb + SM_A_HI + offA);
                ldsm4(al[0], al[1], al[2], al[3], sb + SM_A_LO + offA);
                mma16816(acc, ah, bhf[ksi]);
                mma16816(acc, ah, blf[ksi]);
                mma16816(acc, al, bhf[ksi]);
            }
            int r0 = mt * 16 + nrow_l;
            if (r0 < N_TOK) {
                float2 v; v.x = acc[0] + b0; v.y = acc[1] + b1;
                *reinterpret_cast<float2*>(ost + r0 * 100 + colb) = v;
            }
            int r1 = r0 + 8;
            if (r1 < N_TOK) {
                float2 v; v.x = acc[2] + b0; v.y = acc[3] + b1;
                *reinterpret_cast<float2*>(ost + r1 * 100 + colb) = v;
            }
        }
    }
    __syncthreads();

    // ---- coalesced final store ----
    {
        float4* og = reinterpret_cast<float4*>(out + base);
        for (int i = tid; i < N_TOK * (C_DIM / 4); i += NTHREADS) {
            int row = i / (C_DIM / 4), q = i - row * (C_DIM / 4);
            og[i] = *reinterpret_cast<const float4*>(ost + row * 100 + 4 * q);
        }
    }
}

// ---------------- launch ----------------
extern "C" void kernel_launch(void* const* d_in, const int* in_sizes, int n_in,
                              void* d_out, int out_size) {
    const float* x      = (const float*)d_in[0];
    const float* qkv_w  = (const float*)d_in[1];
    const float* qkv_b  = (const float*)d_in[2];
    const float* proj_w = (const float*)d_in[3];
    const float* proj_b = (const float*)d_in[4];
    const float* table  = (const float*)d_in[5];
    const int*   rel    = (const int*)d_in[6];
    float* out = (float*)d_out;

    cudaFuncSetAttribute(win_attn_mma,
                         cudaFuncAttributeMaxDynamicSharedMemorySize, SMEM_BYTES);

    int ntot = 288 * 96 + 96 * 96 + NHEAD * N_TOK * N_TOK;
    prep_all_kernel<<<(ntot + 255) / 256, 256>>>(qkv_w, proj_w, table, rel);
    win_attn_mma<<<4096, NTHREADS, SMEM_BYTES>>>(x, qkv_b, proj_b, out);
}